// round 7
// baseline (speedup 1.0000x reference)
#include <cuda_runtime.h>
#include <stdint.h>

#define HWC    (512*512)
#define NCH    64
#define NSEG   256
#define NB     4
#define CG     16            // channels per block
#define NCG    4
#define CHUNK  4096          // pixels per block = 8 image rows
#define NCHP   (HWC/CHUNK)   // 64 chunks per plane
#define TPB    256
#define NWARP  8
#define STRIP  512           // px per warp = one image row
#define TPX    64            // px per warp tile-pair
#define NT2    (STRIP/TPX)   // 8 tile-pairs per warp
#define TROW   36            // value row stride u32: 36%32=4 -> uniform banks
#define HBLK   (CG*TROW)     // 576 u32 per px-half block
#define TILE_W (2*HBLK)      // 1152 u32 per warp tile

// Partial tables (encoded u32): [b][g][chunk][c(16)][s(256)]  16.8MB
__device__ unsigned g_scratch[(size_t)NB * NCG * NCHP * CG * NSEG];

// Monotone float->uint encoding; enc >= 1 for any non-NaN float, 0 = identity.
__device__ __forceinline__ unsigned enc_f32(float f) {
    unsigned b = __float_as_uint(f);
    return b ^ ((unsigned)((int)b >> 31) | 0x80000000u);
}

__global__ void __launch_bounds__(TPB, 4) seg_kernel(
    const float* __restrict__ feats,   // [B, C, 512, 512]
    const int*   __restrict__ labels)  // [B, 1, 512, 512]
{
    __shared__ unsigned smax[CG * 257];          // 16.4KB; stride 257
    __shared__ unsigned tiles[NWARP * TILE_W];   // 36.9KB; per-warp [2][16][36]

    const int tid  = threadIdx.x;
    const int lane = tid & 31;
    const int w    = tid >> 5;
    unsigned* tile = tiles + w * TILE_W;

    const int chunk = blockIdx.x;
    const int g     = blockIdx.y;
    const int b     = blockIdx.z;
    const int row   = chunk * NWARP + w;         // this warp's image row
    const int sbase = row * 512;
    const bool ybad = (row == 0) | (row == 511);

    for (int i = tid; i < CG * 257; i += TPB) smax[i] = 0u;
    __syncthreads();

    const int*   lb = labels + (size_t)b * HWC;
    const float* fb = feats + (size_t)(b * NCH + g * CG) * HWC;

    // --- Stage strip labels once: packed u8 into tile-row pad (cols 32..35).
    // Label word k (px 4k..4k+3) lives at tile[(k>>2)*36 + 32 + (k&3)].
    {
        const int4* lbv = (const int4*)(lb + sbase);
        #pragma unroll
        for (int j = 0; j < 4; ++j) {
            int4 l4 = lbv[lane + 32 * j];
            unsigned wd = (unsigned)(l4.x & 255) | ((unsigned)(l4.y & 255) << 8) |
                          ((unsigned)(l4.z & 255) << 16) | ((unsigned)l4.w << 24);
            int k = lane + 32 * j;
            tile[(k >> 2) * TROW + 32 + (k & 3)] = wd;
        }
    }

    // Prefetch tile-pair 0 values (lane holds px {2*lane, 2*lane+1}).
    float2 r2[CG];
    {
        const float* fp = fb + sbase + 2 * lane;
        #pragma unroll
        for (int c = 0; c < CG; ++c)
            r2[c] = *(const float2*)(fp + (size_t)c * HWC);
    }
    __syncwarp();

    const int cs = lane & 15;                 // process-phase channel
    const int h  = lane >> 4;                 // px half (32 px each)
    unsigned* rowp = smax + cs * 257;

    const int hl    = lane >> 4;              // staging half of px pair
    const int soff  = hl * HBLK + 2 * (lane & 15);

    for (int t = 0; t < NT2; ++t) {
        // --- STS phase: encode + border mask current values into tile ---
        {
            const bool bad0 = ybad | ((t == 0) & (lane == 0));
            const bool bad1 = ybad | ((t == NT2 - 1) & (lane == 31));
            #pragma unroll
            for (int c = 0; c < CG; ++c) {
                uint2 e;
                e.x = bad0 ? 0u : enc_f32(r2[c].x);
                e.y = bad1 ? 0u : enc_f32(r2[c].y);
                *(uint2*)(tile + c * TROW + soff) = e;
            }
        }
        __syncwarp();

        // --- Prefetch next tile-pair ---
        if (t + 1 < NT2) {
            const float* fp = fb + sbase + (t + 1) * TPX + 2 * lane;
            #pragma unroll
            for (int c = 0; c < CG; ++c)
                r2[c] = *(const float2*)(fp + (size_t)c * HWC);
        }

        // --- Process phase: lane = (h, cs); 32 px of own half, no SHFL ---
        {
            const uint4* vrow = (const uint4*)(tile + h * HBLK + cs * TROW);
            const int m  = 2 * t + h;               // 32-px label group index
            uint4 La = *(const uint4*)(tile + (2 * m)     * TROW + 32);
            uint4 Lb = *(const uint4*)(tile + (2 * m + 1) * TROW + 32);
            unsigned lw[8] = {La.x, La.y, La.z, La.w, Lb.x, Lb.y, Lb.z, Lb.w};
            #pragma unroll
            for (int q = 0; q < 8; ++q) {
                uint4 e = vrow[q];
                unsigned wd = lw[q];
                atomicMax(rowp + (wd & 255),         e.x);
                atomicMax(rowp + ((wd >> 8) & 255),  e.y);
                atomicMax(rowp + ((wd >> 16) & 255), e.z);
                atomicMax(rowp + (wd >> 24),         e.w);
            }
        }
        __syncwarp();
    }

    __syncthreads();
    // Dump private table to scratch (non-atomic, coalesced).
    unsigned* dst = g_scratch + (size_t)((b * NCG + g) * NCHP + chunk) * (CG * NSEG);
    for (int i = tid; i < CG * NSEG; i += TPB)
        dst[i] = smax[(i >> 8) * 257 + (i & 255)];
}

// Block per (b,g,c); thread = segment; 64 fully-coalesced k-rows of 1KB.
__global__ void __launch_bounds__(TPB) reduce_kernel(float* __restrict__ out) {
    const int x = blockIdx.x;                 // 0..255
    const int c = x & 15;
    const int g = (x >> 4) & 3;
    const int b = x >> 6;
    const int s = threadIdx.x;

    const unsigned* src = g_scratch
        + (size_t)((b * NCG + g) * NCHP) * (CG * NSEG) + c * NSEG + s;

    unsigned m0 = 0, m1 = 0, m2 = 0, m3 = 0;
    #pragma unroll 4
    for (int k = 0; k < NCHP; k += 4) {
        m0 = max(m0, src[(size_t)(k + 0) * (CG * NSEG)]);
        m1 = max(m1, src[(size_t)(k + 1) * (CG * NSEG)]);
        m2 = max(m2, src[(size_t)(k + 2) * (CG * NSEG)]);
        m3 = max(m3, src[(size_t)(k + 3) * (CG * NSEG)]);
    }
    unsigned m = max(max(m0, m1), max(m2, m3));

    float rv;
    if (m == 0u) {
        rv = 0.0f;
    } else {
        unsigned bits = (m & 0x80000000u) ? (m ^ 0x80000000u) : ~m;
        rv = __uint_as_float(bits);
    }
    out[(size_t)(b * NCH + g * CG + c) * NSEG + s] = rv;
}

// Keeps ncu's fixed capture slot landing on seg_kernel.
__global__ void nop_kernel() {}

extern "C" void kernel_launch(void* const* d_in, const int* in_sizes, int n_in,
                              void* d_out, int out_size) {
    const float* feats  = (const float*)d_in[0];
    const int*   labels = (const int*)d_in[1];
    float*       out    = (float*)d_out;

    dim3 grid(NCHP, NCG, NB);                 // (64, 4, 4) = 1024 blocks
    seg_kernel<<<grid, TPB>>>(feats, labels);

    reduce_kernel<<<NB * NCG * CG, TPB>>>(out);

    nop_kernel<<<1, 32>>>();
}

// round 8
// speedup vs baseline: 1.1175x; 1.1175x over previous
#include <cuda_runtime.h>
#include <stdint.h>

#define HWC    (512*512)
#define NCH    64
#define NSEG   256
#define NB     4
#define CG     16            // channels per block
#define NCG    4
#define CHUNK  4096          // pixels per block = 8 image rows
#define NCHP   (HWC/CHUNK)   // 64 chunks per plane
#define TPB    256
#define NWARP  8
#define STRIP  512           // px per warp = one image row
#define TPX    32            // px per warp-tile
#define NT     (STRIP/TPX)   // 16 tiles per warp
#define TROW   44            // tile row stride u32
#define LSTR   132           // label words per warp (128 + 4 pad)

// Partial tables (encoded u32): [b][g][chunk][c(16)][s(256)]  16.8MB
__device__ unsigned g_scratch[(size_t)NB * NCG * NCHP * CG * NSEG];
// k-split partials for two-stage reduce: [4][b][g][c][s]  1MB
__device__ unsigned g_part[4 * NB * NCG * CG * NSEG];

// Monotone float->uint encoding; enc >= 1 for any non-NaN float, 0 = identity.
__device__ __forceinline__ unsigned enc_f32(float f) {
    unsigned b = __float_as_uint(f);
    return b ^ ((unsigned)((int)b >> 31) | 0x80000000u);
}

__global__ void __launch_bounds__(TPB, 5) seg_kernel(
    const float* __restrict__ feats,   // [B, C, 512, 512]
    const int*   __restrict__ labels)  // [B, 1, 512, 512]
{
    __shared__ unsigned smax[CG * 257];            // 16.4KB, stride 257
    __shared__ unsigned tiles[NWARP * CG * TROW];  // 22.0KB, per-warp [16][44]
    __shared__ unsigned labs[NWARP * LSTR];        //  4.2KB, packed u8 labels

    const int tid  = threadIdx.x;
    const int lane = tid & 31;
    const int w    = tid >> 5;
    unsigned* tile = tiles + w * (CG * TROW);
    unsigned* lrow = labs + w * LSTR;

    const int chunk = blockIdx.x;
    const int g     = blockIdx.y;
    const int b     = blockIdx.z;
    const int row   = chunk * NWARP + w;           // this warp's image row
    const int sbase = row * 512;
    const bool ybad = (row == 0) | (row == 511);

    for (int i = tid; i < CG * 257; i += TPB) smax[i] = 0u;
    __syncthreads();

    const int*   lb = labels + (size_t)b * HWC;
    const float* fb = feats + (size_t)(b * NCH + g * CG) * HWC;

    // --- Stage strip labels once: 512 labels -> 128 packed u32 words ---
    {
        const int4* lbv = (const int4*)(lb + sbase);
        #pragma unroll
        for (int j = 0; j < 4; ++j) {
            int4 l4 = lbv[lane + 32 * j];
            lrow[lane + 32 * j] =
                (unsigned)(l4.x & 255) | ((unsigned)(l4.y & 255) << 8) |
                ((unsigned)(l4.z & 255) << 16) | ((unsigned)l4.w << 24);
        }
    }

    // Prefetch tile 0 (lane = pixel).
    float r[CG];
    {
        const int p = sbase + lane;
        #pragma unroll
        for (int c = 0; c < CG; ++c) r[c] = fb[(size_t)c * HWC + p];
    }
    __syncwarp();

    const int cs = lane & 15;                 // process-phase channel
    const int h  = lane >> 4;                 // px half (0: px 0-15, 1: 16-31)
    unsigned*    rowp = smax + cs * 257;
    const uint4* trow = (const uint4*)(tile + cs * TROW) + h * 4;

    for (int t = 0; t < NT; ++t) {
        // --- STS phase (lane = pixel): encode + border mask into warp tile ---
        {
            const bool bad = ybad | ((t == 0) & (lane == 0)) |
                                    ((t == NT - 1) & (lane == 31));
            #pragma unroll
            for (int c = 0; c < CG; ++c)
                tile[c * TROW + lane] = bad ? 0u : enc_f32(r[c]);
        }
        __syncwarp();

        // --- Prefetch next tile ---
        if (t + 1 < NT) {
            const int p = sbase + (t + 1) * TPX + lane;
            #pragma unroll
            for (int c = 0; c < CG; ++c) r[c] = fb[(size_t)c * HWC + p];
        }

        // --- Process phase: lane = (h, cs); labels via 1 broadcast LDS.128 ---
        {
            const uint4 L = *(const uint4*)(lrow + t * 8 + h * 4);
            const unsigned lw[4] = {L.x, L.y, L.z, L.w};
            #pragma unroll
            for (int q = 0; q < 4; ++q) {
                uint4 e = trow[q];
                unsigned wd = lw[q];
                atomicMax(rowp + (wd & 255),         e.x);
                atomicMax(rowp + ((wd >> 8) & 255),  e.y);
                atomicMax(rowp + ((wd >> 16) & 255), e.z);
                atomicMax(rowp + (wd >> 24),         e.w);
            }
        }
        __syncwarp();
    }

    __syncthreads();
    // Dump private table to scratch (non-atomic, coalesced).
    unsigned* dst = g_scratch + (size_t)((b * NCG + g) * NCHP + chunk) * (CG * NSEG);
    for (int i = tid; i < CG * NSEG; i += TPB)
        dst[i] = smax[(i >> 8) * 257 + (i & 255)];
}

// Stage 1: block = (b,g,c,kq); thread = segment; 16 coalesced 1KB k-rows.
__global__ void __launch_bounds__(TPB) reduce1_kernel() {
    const int x  = blockIdx.x;                // 0..1023
    const int kq = x & 3;
    const int c  = (x >> 2) & 15;
    const int g  = (x >> 6) & 3;
    const int b  = x >> 8;
    const int s  = threadIdx.x;

    const unsigned* src = g_scratch
        + (size_t)((b * NCG + g) * NCHP + kq * 16) * (CG * NSEG) + c * NSEG + s;

    unsigned m0 = 0, m1 = 0, m2 = 0, m3 = 0;
    #pragma unroll
    for (int k = 0; k < 16; k += 4) {
        m0 = max(m0, src[(size_t)(k + 0) * (CG * NSEG)]);
        m1 = max(m1, src[(size_t)(k + 1) * (CG * NSEG)]);
        m2 = max(m2, src[(size_t)(k + 2) * (CG * NSEG)]);
        m3 = max(m3, src[(size_t)(k + 3) * (CG * NSEG)]);
    }
    const int e = ((b * NCG + g) * CG + c) * NSEG + s;   // == out element index
    g_part[kq * (NB * NCG * CG * NSEG) + e] = max(max(m0, m1), max(m2, m3));
}

// Stage 2: thread per output element; max 4 partials, decode, empty->0.
__global__ void __launch_bounds__(TPB) reduce2_kernel(float* __restrict__ out) {
    const int e = blockIdx.x * TPB + threadIdx.x;        // 0..65535
    const int NE = NB * NCG * CG * NSEG;
    unsigned m = max(max(g_part[e], g_part[NE + e]),
                     max(g_part[2 * NE + e], g_part[3 * NE + e]));
    float rv;
    if (m == 0u) {
        rv = 0.0f;
    } else {
        unsigned bits = (m & 0x80000000u) ? (m ^ 0x80000000u) : ~m;
        rv = __uint_as_float(bits);
    }
    out[e] = rv;   // [b][g][c][s] flattening == [b][ch][s] with ch = g*16+c
}

extern "C" void kernel_launch(void* const* d_in, const int* in_sizes, int n_in,
                              void* d_out, int out_size) {
    const float* feats  = (const float*)d_in[0];
    const int*   labels = (const int*)d_in[1];
    float*       out    = (float*)d_out;

    dim3 grid(NCHP, NCG, NB);                 // (64, 4, 4) = 1024 blocks
    seg_kernel<<<grid, TPB>>>(feats, labels);

    reduce1_kernel<<<NB * NCG * CG * 4, TPB>>>();
    reduce2_kernel<<<(NB * NCH * NSEG) / TPB, TPB>>>(out);
}